// round 14
// baseline (speedup 1.0000x reference)
#include <cuda_runtime.h>
#include <cuda.h>
#include <cstdint>
#include <math.h>

#define B_SLIDES 64
#define N_CELLS  20000
#define NI       64
#define H1       16
#define H2       8
#define N_OUT    2

#define TPB      128                 // 4 warps
#define CSTAGE   128                 // cells per tile (1 per thread)
#define CHUNKS   13
#define CELLS_PER_CHUNK ((N_CELLS + CHUNKS - 1) / CHUNKS)   // 1539
#define TOTAL_BLOCKS (CHUNKS * B_SLIDES)                    // 832 (<= 6*148=888, one wave)

// Staging: two TMA halves, each 128 rows x 128 bytes (SW128-swizzled by TMA HW)
#define XS_HALF  16384
#define XS_BYTES (2 * XS_HALF)       // 32768
// 1024 alignment slack + xs + W1-highhalf(2KB) + W2(512) + tails
#define SMEM_BYTES (1024 + XS_BYTES + 2048 + 512 + 32 + 32 + 160)

typedef unsigned long long ull;

// ---- W1 (+b1) in constant memory: j 0..7 come from the constant port ----
__constant__ ull   cW1p[NI * H1 / 2];   // W1[64][16] raw -> [64][8] fp32-pairs (4KB)
__constant__ float cb1[H1];

__device__ float        g_partials[B_SLIDES * CHUNKS * 9];
__device__ unsigned int g_count = 0;

__device__ __forceinline__ ull pack2(float lo, float hi) {
    ull r; asm("mov.b64 %0, {%1, %2};" : "=l"(r) : "f"(lo), "f"(hi)); return r;
}
__device__ __forceinline__ void unpack2(ull v, float& lo, float& hi) {
    asm("mov.b64 {%0, %1}, %2;" : "=f"(lo), "=f"(hi) : "l"(v));
}
// Packed fp32x2 FMA (sm_100+): two fp32 FMAs per instruction.
__device__ __forceinline__ ull fma2(ull a, ull b, ull c) {
    ull d; asm("fma.rn.f32x2 %0, %1, %2, %3;" : "=l"(d) : "l"(a), "l"(b), "l"(c)); return d;
}
__device__ __forceinline__ float ldcg(const float* p) {
    float v; asm("ld.global.cg.f32 %0, [%1];" : "=f"(v) : "l"(p)); return v;
}

__device__ __forceinline__ void mbar_init(uint32_t a, uint32_t cnt) {
    asm volatile("mbarrier.init.shared.b64 [%0], %1;" :: "r"(a), "r"(cnt) : "memory");
}
__device__ __forceinline__ void mbar_expect_tx(uint32_t a, uint32_t bytes) {
    asm volatile("mbarrier.arrive.expect_tx.shared.b64 _, [%0], %1;"
                 :: "r"(a), "r"(bytes) : "memory");
}
__device__ __forceinline__ void mbar_wait(uint32_t a, uint32_t phase) {
    asm volatile(
        "{\n\t.reg .pred P;\n"
        "WAIT_%=:\n\t"
        "mbarrier.try_wait.parity.shared.b64 P, [%0], %1;\n\t"
        "@P bra DONE_%=;\n\t"
        "bra WAIT_%=;\n"
        "DONE_%=:\n\t}"
        :: "r"(a), "r"(phase) : "memory");
}
__device__ __forceinline__ void tma_load_3d(uint32_t dst, const CUtensorMap* tm,
                                            int x, int y, int z, uint32_t mbar) {
    asm volatile(
        "cp.async.bulk.tensor.3d.shared::cta.global.tile.mbarrier::complete_tx::bytes "
        "[%0], [%1, {%2, %3, %4}], [%5];"
        :: "r"(dst), "l"(tm), "r"(x), "r"(y), "r"(z), "r"(mbar) : "memory");
}

__global__ __launch_bounds__(TPB, 6) void mlp_pool_kernel(
    const __grid_constant__ CUtensorMap tmap,
    const float* __restrict__ W1,
    const float* __restrict__ W2, const float* __restrict__ b2,
    const float* __restrict__ Ww, const float* __restrict__ bw,
    const float* __restrict__ W4, const float* __restrict__ b4,
    float* __restrict__ out)
{
    extern __shared__ char smem_raw[];
    // TMA SW128 destination must be 1024B-aligned
    char* xs = (char*)(((uintptr_t)smem_raw + 1023) & ~(uintptr_t)1023);
    ull*   w1s = (ull*)(xs + XS_BYTES);                   // 256 ull: W1 j=8..15 halves
    ull*   w2q = w1s + 256;                               // 64 ull (W2 raw pairs)
    ull*   wwp = w2q + 64;                                // 4 ull
    float* b2s = (float*)(wwp + 4);                       // 8
    float* red = b2s + 8;                                 // 9 * 4
    __shared__ uint64_t s_mbar;
    __shared__ unsigned int s_last;

    const int tid   = threadIdx.x;
    const int b     = blockIdx.y;
    const int chunk = blockIdx.x;

    const uint32_t xs_smem = (uint32_t)__cvta_generic_to_shared(xs);
    const uint32_t mb      = (uint32_t)__cvta_generic_to_shared(&s_mbar);

    // ---- weights -> SMEM: only W1's j=8..15 half (const port serves j=0..7) ----
    {
        const ull* W1q = (const ull*)W1;                  // [64][8] pairs
        for (int k = tid; k < 256; k += TPB) {
            int i = k >> 2, q = k & 3;
            w1s[k] = W1q[i * 8 + 4 + q];
        }
    }
    if (tid < 64) w2q[tid] = ((const ull*)W2)[tid];
    if (tid < 4)  wwp[tid] = ((const ull*)Ww)[tid];
    if (tid < 8)  b2s[tid] = b2[tid];
    if (tid == 0) mbar_init(mb, 1);
    const float bwv = __ldg(bw);

    const int start = chunk * CELLS_PER_CHUNK;
    const int end   = min(start + CELLS_PER_CHUNK, N_CELLS);

    float sw = 0.f;
    ull swh[4];
    #pragma unroll
    for (int k = 0; k < 4; ++k) swh[k] = pack2(0.f, 0.f);

    int phase = 0;
    for (int base = start; base < end; base += CSTAGE) {
        __syncthreads();                 // weights/mbar init + buffer fully consumed

        // ---- one TMA tile: 128 cells x 64 floats, two SW128 halves ----
        if (tid == 0) {
            mbar_expect_tx(mb, XS_BYTES);
            tma_load_3d(xs_smem,           &tmap, 0,  base, b, mb);
            tma_load_3d(xs_smem + XS_HALF, &tmap, 32, base, b, mb);
        }
        mbar_wait(mb, phase);
        phase ^= 1;

        const int nv = min(end - base, CSTAGE);
        const bool valid = (tid < nv);   // OOB rows are TMA zero-filled

        // ---- layer 1: 64 -> 16; weights split across const + SMEM ports ----
        ull acc[8];
        #pragma unroll
        for (int jp = 0; jp < 8; ++jp)
            acc[jp] = pack2(cb1[2 * jp], cb1[2 * jp + 1]);

        #pragma unroll 4
        for (int i4 = 0; i4 < 16; ++i4) {
            // SW128 swizzle within 128B rows: chunk' = c16 ^ (row & 7)
            const char* hx = xs + ((i4 < 8) ? 0 : XS_HALF);
            int c16 = i4 & 7;
            float4 xv = *(const float4*)(hx + (tid << 7) + ((c16 ^ (tid & 7)) << 4));
            #pragma unroll
            for (int s = 0; s < 4; ++s) {
                int i = i4 * 4 + s;
                float xc = (s == 0) ? xv.x : (s == 1) ? xv.y : (s == 2) ? xv.z : xv.w;
                ull x2 = pack2(xc, xc);
                const ulonglong2* wrc = (const ulonglong2*)&cW1p[i * 8];      // j 0..7
                const ulonglong2* wrs = (const ulonglong2*)&w1s[i * 4];       // j 8..15
                ulonglong2 wa = wrc[0], wb = wrc[1];
                ulonglong2 wc = wrs[0], wd = wrs[1];
                acc[0] = fma2(x2, wa.x, acc[0]);
                acc[1] = fma2(x2, wa.y, acc[1]);
                acc[2] = fma2(x2, wb.x, acc[2]);
                acc[3] = fma2(x2, wb.y, acc[3]);
                acc[4] = fma2(x2, wc.x, acc[4]);
                acc[5] = fma2(x2, wc.y, acc[5]);
                acc[6] = fma2(x2, wd.x, acc[6]);
                acc[7] = fma2(x2, wd.y, acc[7]);
            }
        }

        // ---- per-cell tail: relu -> layer2 -> relu -> gate -> accumulate ----
        float h1[H1];
        #pragma unroll
        for (int jp = 0; jp < 8; ++jp) {
            float lo, hi; unpack2(acc[jp], lo, hi);
            h1[2 * jp]     = fmaxf(lo, 0.f);
            h1[2 * jp + 1] = fmaxf(hi, 0.f);
        }

        ull acc2[4];
        #pragma unroll
        for (int kp = 0; kp < 4; ++kp) acc2[kp] = pack2(b2s[2 * kp], b2s[2 * kp + 1]);
        const ulonglong2* w2p = (const ulonglong2*)w2q;
        #pragma unroll
        for (int i = 0; i < H1; ++i) {
            ull hx2 = pack2(h1[i], h1[i]);
            ulonglong2 wa = w2p[i * 2 + 0];
            ulonglong2 wb = w2p[i * 2 + 1];
            acc2[0] = fma2(hx2, wa.x, acc2[0]);
            acc2[1] = fma2(hx2, wa.y, acc2[1]);
            acc2[2] = fma2(hx2, wb.x, acc2[2]);
            acc2[3] = fma2(hx2, wb.y, acc2[3]);
        }

        float h2[H2];
        #pragma unroll
        for (int kp = 0; kp < 4; ++kp) {
            float lo, hi; unpack2(acc2[kp], lo, hi);
            h2[2 * kp]     = fmaxf(lo, 0.f);
            h2[2 * kp + 1] = fmaxf(hi, 0.f);
        }

        ull g = pack2(bwv, 0.f);
        #pragma unroll
        for (int kp = 0; kp < 4; ++kp)
            g = fma2(pack2(h2[2 * kp], h2[2 * kp + 1]), wwp[kp], g);
        float glo, ghi; unpack2(g, glo, ghi);
        float wgt = 1.f / (1.f + __expf(-(glo + ghi)));
        if (!valid) wgt = 0.f;

        sw += wgt;
        ull wp = pack2(wgt, wgt);
        #pragma unroll
        for (int kp = 0; kp < 4; ++kp)
            swh[kp] = fma2(wp, pack2(h2[2 * kp], h2[2 * kp + 1]), swh[kp]);
    }

    // ---- deterministic block reduction of 9 values (4 warps) ----
    float vals[9];
    vals[0] = sw;
    #pragma unroll
    for (int kp = 0; kp < 4; ++kp) {
        float lo, hi; unpack2(swh[kp], lo, hi);
        vals[1 + 2 * kp] = lo; vals[2 + 2 * kp] = hi;
    }
    #pragma unroll
    for (int off = 16; off > 0; off >>= 1) {
        #pragma unroll
        for (int k = 0; k < 9; ++k)
            vals[k] += __shfl_down_sync(0xffffffffu, vals[k], off);
    }
    const int lane = tid & 31, warp = tid >> 5;
    if (lane == 0) {
        #pragma unroll
        for (int k = 0; k < 9; ++k) red[k * 4 + warp] = vals[k];
    }
    __syncthreads();
    if (tid < 9) {
        float s = 0.f;
        #pragma unroll
        for (int w = 0; w < 4; ++w) s += red[tid * 4 + w];
        g_partials[((size_t)b * CHUNKS + chunk) * 9 + tid] = s;
    }

    // ---- last-block finalize (fused head; graph-replay-safe counter) ----
    __threadfence();
    __syncthreads();
    if (tid == 0) {
        unsigned int d = atomicAdd(&g_count, 1u);
        s_last = (d == TOTAL_BLOCKS - 1) ? 1u : 0u;
    }
    __syncthreads();

    if (s_last) {
        float* fs = (float*)xs;          // reuse staging buffer: [64][9]
        for (int p = tid; p < B_SLIDES * 9; p += TPB) {
            int bb = p / 9, k = p % 9;
            float s = 0.f;
            #pragma unroll
            for (int c = 0; c < CHUNKS; ++c)
                s += ldcg(&g_partials[((size_t)bb * CHUNKS + c) * 9 + k]);
            fs[bb * 9 + k] = s;
        }
        __syncthreads();
        if (tid < B_SLIDES) {
            float inv = 1.f / fs[tid * 9];
            #pragma unroll
            for (int o = 0; o < N_OUT; ++o) {
                float r = b4[o];
                #pragma unroll
                for (int k = 0; k < H2; ++k)
                    r += (fs[tid * 9 + 1 + k] * inv) * W4[k * N_OUT + o];
                out[tid * N_OUT + o] = r;
            }
        }
        if (tid == 0) atomicExch(&g_count, 0u);   // reset for next graph replay
    }
}

typedef CUresult (*EncodeFn)(
    CUtensorMap*, CUtensorMapDataType, cuuint32_t, void*,
    const cuuint64_t*, const cuuint64_t*, const cuuint32_t*, const cuuint32_t*,
    CUtensorMapInterleave, CUtensorMapSwizzle, CUtensorMapL2promotion,
    CUtensorMapFloatOOBfill);

extern "C" void kernel_launch(void* const* d_in, const int* in_sizes, int n_in,
                              void* d_out, int out_size)
{
    (void)in_sizes; (void)n_in; (void)out_size;

    // W1 + b1 into constant memory (raw D2D copies, graph-capturable).
    cudaMemcpyToSymbolAsync(cW1p, d_in[1], NI * H1 * sizeof(float), 0,
                            cudaMemcpyDeviceToDevice, 0);
    cudaMemcpyToSymbolAsync(cb1,  d_in[2], H1 * sizeof(float), 0,
                            cudaMemcpyDeviceToDevice, 0);

    // Build the TMA descriptor on host (pure host work; no link dep on libcuda).
    void* pfn = nullptr;
    cudaDriverEntryPointQueryResult qres;
    cudaGetDriverEntryPoint("cuTensorMapEncodeTiled", &pfn,
                            cudaEnableDefault, &qres);
    EncodeFn encode = (EncodeFn)pfn;

    CUtensorMap tmap;
    cuuint64_t gdims[3]   = {NI, N_CELLS, B_SLIDES};
    cuuint64_t gstrides[2] = {NI * sizeof(float),
                              (cuuint64_t)N_CELLS * NI * sizeof(float)};
    cuuint32_t box[3]     = {32, CSTAGE, 1};    // 32 f32 = 128B (SW128 limit)
    cuuint32_t estr[3]    = {1, 1, 1};
    encode(&tmap, CU_TENSOR_MAP_DATA_TYPE_FLOAT32, 3, d_in[0],
           gdims, gstrides, box, estr,
           CU_TENSOR_MAP_INTERLEAVE_NONE, CU_TENSOR_MAP_SWIZZLE_128B,
           CU_TENSOR_MAP_L2_PROMOTION_L2_128B,
           CU_TENSOR_MAP_FLOAT_OOB_FILL_NONE);

    cudaFuncSetAttribute(mlp_pool_kernel,
                         cudaFuncAttributeMaxDynamicSharedMemorySize, SMEM_BYTES);
    dim3 grid(CHUNKS, B_SLIDES);
    mlp_pool_kernel<<<grid, TPB, SMEM_BYTES>>>(
        tmap,
        (const float*)d_in[1],
        (const float*)d_in[3], (const float*)d_in[4],
        (const float*)d_in[5], (const float*)d_in[6],
        (const float*)d_in[7], (const float*)d_in[8],
        (float*)d_out);
}

// round 15
// speedup vs baseline: 1.3618x; 1.3618x over previous
#include <cuda_runtime.h>
#include <cstdint>
#include <math.h>

#define B_SLIDES 64
#define N_CELLS  20000
#define NI       64
#define H1       16
#define H2       8
#define N_OUT    2

#define TPB      128                 // 4 warps; each warp owns its own pipeline
#define WTILE    32                  // cells per warp-tile (1 per lane)
#define CHUNKS   13
#define CELLS_PER_CHUNK ((N_CELLS + CHUNKS - 1) / CHUNKS)   // 1539
#define TOTAL_BLOCKS (CHUNKS * B_SLIDES)                    // 832 (<= 6*148=888, one wave)

#define WBUF_BYTES 8192              // 32 cells x 256B, per-warp staging quadrant
#define XS_BYTES (4 * WBUF_BYTES)    // 32768
#define SMEM_BYTES (XS_BYTES + 2048 + 512 + 32 + 32 + 160 + 64)

typedef unsigned long long ull;

// ---- W1 (+b1) in constant memory: j 0..7 served by the constant port ----
__constant__ ull   cW1p[NI * H1 / 2];   // W1[64][16] raw -> [64][8] fp32-pairs (4KB)
__constant__ float cb1[H1];

__device__ float        g_partials[B_SLIDES * CHUNKS * 9];
__device__ unsigned int g_count = 0;

__device__ __forceinline__ ull pack2(float lo, float hi) {
    ull r; asm("mov.b64 %0, {%1, %2};" : "=l"(r) : "f"(lo), "f"(hi)); return r;
}
__device__ __forceinline__ void unpack2(ull v, float& lo, float& hi) {
    asm("mov.b64 {%0, %1}, %2;" : "=f"(lo), "=f"(hi) : "l"(v));
}
// Packed fp32x2 FMA (sm_100+): two fp32 FMAs per instruction.
__device__ __forceinline__ ull fma2(ull a, ull b, ull c) {
    ull d; asm("fma.rn.f32x2 %0, %1, %2, %3;" : "=l"(d) : "l"(a), "l"(b), "l"(c)); return d;
}
__device__ __forceinline__ float ldcg(const float* p) {
    float v; asm("ld.global.cg.f32 %0, [%1];" : "=f"(v) : "l"(p)); return v;
}

// 256B rows, 16B chunks: chunk' = col16 ^ (row & 7) -> conflict-free R/W
__device__ __forceinline__ uint32_t xs_off(int row, int col16) {
    return ((uint32_t)row << 8) + (((uint32_t)(col16 ^ (row & 7))) << 4);
}

__global__ __launch_bounds__(TPB, 6) void mlp_pool_kernel(
    const float* __restrict__ X,
    const float* __restrict__ W1,
    const float* __restrict__ W2, const float* __restrict__ b2,
    const float* __restrict__ Ww, const float* __restrict__ bw,
    const float* __restrict__ W4, const float* __restrict__ b4,
    float* __restrict__ out)
{
    extern __shared__ char smem[];
    char*  xs  = smem;                                    // 4 x 8KB warp quadrants
    ull*   w1s = (ull*)(smem + XS_BYTES);                 // 256 ull: W1 j=8..15 halves
    ull*   w2q = w1s + 256;                               // 64 ull (W2 raw pairs)
    ull*   wwp = w2q + 64;                                // 4 ull
    float* b2s = (float*)(wwp + 4);                       // 8
    float* red = b2s + 8;                                 // 9 * 4
    __shared__ unsigned int s_last;

    const int tid  = threadIdx.x;
    const int wid  = tid >> 5;
    const int lane = tid & 31;
    const int b     = blockIdx.y;
    const int chunk = blockIdx.x;

    char* wbuf = xs + wid * WBUF_BYTES;
    const uint32_t wbuf_s = (uint32_t)__cvta_generic_to_shared(wbuf);

    // ---- weights -> SMEM (W1 j=8..15 half; const port covers j=0..7) ----
    {
        const ull* W1q = (const ull*)W1;                  // [64][8] pairs
        for (int k = tid; k < 256; k += TPB) {
            int i = k >> 2, q = k & 3;
            w1s[k] = W1q[i * 8 + 4 + q];
        }
    }
    if (tid < 64) w2q[tid] = ((const ull*)W2)[tid];
    if (tid < 4)  wwp[tid] = ((const ull*)Ww)[tid];
    if (tid < 8)  b2s[tid] = b2[tid];
    const float bwv = __ldg(bw);
    __syncthreads();                   // ONLY block barrier before the reduction

    const int start = chunk * CELLS_PER_CHUNK;
    const int end   = min(start + CELLS_PER_CHUNK, N_CELLS);

    const float4* __restrict__ Xg = (const float4*)(X + (size_t)b * N_CELLS * NI);

    float sw = 0.f;
    ull swh[4];
    #pragma unroll
    for (int k = 0; k < 4; ++k) swh[k] = pack2(0.f, 0.f);

    // ---- fully decoupled per-warp pipeline: no block barriers in this loop ----
    for (int base = start + wid * WTILE; base < end; base += TPB) {

        // stage this warp's 32 cells (8KB, each warp-instr = 512B contiguous)
        #pragma unroll
        for (int k = 0; k < 16; ++k) {
            int f = lane + k * 32;            // 0..511
            int c = f >> 4;                   // row 0..31
            int o = f & 15;                   // float4 slot
            int n = base + c;
            if (n > end - 1) n = end - 1;     // clamp (gated by valid below)
            uint32_t dst = wbuf_s + xs_off(c, o);
            const float4* src = &Xg[(size_t)n * (NI / 4) + o];
            asm volatile("cp.async.cg.shared.global [%0], [%1], 16;"
                         :: "r"(dst), "l"(src));
        }
        asm volatile("cp.async.commit_group;");
        asm volatile("cp.async.wait_group 0;");
        __syncwarp();                         // all lanes' copies complete

        const bool valid = (base + lane) < end;

        // ---- layer 1: 64 -> 16; weights split across const + SMEM ports ----
        ull acc[8];
        #pragma unroll
        for (int jp = 0; jp < 8; ++jp)
            acc[jp] = pack2(cb1[2 * jp], cb1[2 * jp + 1]);

        #pragma unroll 4
        for (int i4 = 0; i4 < 16; ++i4) {
            float4 xv = *(const float4*)(wbuf + xs_off(lane, i4));
            #pragma unroll
            for (int s = 0; s < 4; ++s) {
                int i = i4 * 4 + s;
                float xc = (s == 0) ? xv.x : (s == 1) ? xv.y : (s == 2) ? xv.z : xv.w;
                ull x2 = pack2(xc, xc);
                const ulonglong2* wrc = (const ulonglong2*)&cW1p[i * 8];   // j 0..7
                const ulonglong2* wrs = (const ulonglong2*)&w1s[i * 4];    // j 8..15
                ulonglong2 wa = wrc[0], wb = wrc[1];
                ulonglong2 wc = wrs[0], wd = wrs[1];
                acc[0] = fma2(x2, wa.x, acc[0]);
                acc[1] = fma2(x2, wa.y, acc[1]);
                acc[2] = fma2(x2, wb.x, acc[2]);
                acc[3] = fma2(x2, wb.y, acc[3]);
                acc[4] = fma2(x2, wc.x, acc[4]);
                acc[5] = fma2(x2, wc.y, acc[5]);
                acc[6] = fma2(x2, wd.x, acc[6]);
                acc[7] = fma2(x2, wd.y, acc[7]);
            }
        }
        __syncwarp();                         // reads done before next stage

        // ---- per-cell tail: relu -> layer2 -> relu -> gate -> accumulate ----
        float h1[H1];
        #pragma unroll
        for (int jp = 0; jp < 8; ++jp) {
            float lo, hi; unpack2(acc[jp], lo, hi);
            h1[2 * jp]     = fmaxf(lo, 0.f);
            h1[2 * jp + 1] = fmaxf(hi, 0.f);
        }

        ull acc2[4];
        #pragma unroll
        for (int kp = 0; kp < 4; ++kp) acc2[kp] = pack2(b2s[2 * kp], b2s[2 * kp + 1]);
        const ulonglong2* w2p = (const ulonglong2*)w2q;
        #pragma unroll
        for (int i = 0; i < H1; ++i) {
            ull hx = pack2(h1[i], h1[i]);
            ulonglong2 wa = w2p[i * 2 + 0];
            ulonglong2 wb = w2p[i * 2 + 1];
            acc2[0] = fma2(hx, wa.x, acc2[0]);
            acc2[1] = fma2(hx, wa.y, acc2[1]);
            acc2[2] = fma2(hx, wb.x, acc2[2]);
            acc2[3] = fma2(hx, wb.y, acc2[3]);
        }

        float h2[H2];
        #pragma unroll
        for (int kp = 0; kp < 4; ++kp) {
            float lo, hi; unpack2(acc2[kp], lo, hi);
            h2[2 * kp]     = fmaxf(lo, 0.f);
            h2[2 * kp + 1] = fmaxf(hi, 0.f);
        }

        ull g = pack2(bwv, 0.f);
        #pragma unroll
        for (int kp = 0; kp < 4; ++kp)
            g = fma2(pack2(h2[2 * kp], h2[2 * kp + 1]), wwp[kp], g);
        float glo, ghi; unpack2(g, glo, ghi);
        float wgt = 1.f / (1.f + __expf(-(glo + ghi)));
        if (!valid) wgt = 0.f;

        sw += wgt;
        ull wp = pack2(wgt, wgt);
        #pragma unroll
        for (int kp = 0; kp < 4; ++kp)
            swh[kp] = fma2(wp, pack2(h2[2 * kp], h2[2 * kp + 1]), swh[kp]);
    }

    // ---- deterministic block reduction of 9 values (4 warps) ----
    float vals[9];
    vals[0] = sw;
    #pragma unroll
    for (int kp = 0; kp < 4; ++kp) {
        float lo, hi; unpack2(swh[kp], lo, hi);
        vals[1 + 2 * kp] = lo; vals[2 + 2 * kp] = hi;
    }
    #pragma unroll
    for (int off = 16; off > 0; off >>= 1) {
        #pragma unroll
        for (int k = 0; k < 9; ++k)
            vals[k] += __shfl_down_sync(0xffffffffu, vals[k], off);
    }
    if (lane == 0) {
        #pragma unroll
        for (int k = 0; k < 9; ++k) red[k * 4 + wid] = vals[k];
    }
    __syncthreads();
    if (tid < 9) {
        float s = 0.f;
        #pragma unroll
        for (int w = 0; w < 4; ++w) s += red[tid * 4 + w];
        g_partials[((size_t)b * CHUNKS + chunk) * 9 + tid] = s;
    }

    // ---- last-block finalize (fused head; graph-replay-safe counter) ----
    __threadfence();
    __syncthreads();
    if (tid == 0) {
        unsigned int d = atomicAdd(&g_count, 1u);
        s_last = (d == TOTAL_BLOCKS - 1) ? 1u : 0u;
    }
    __syncthreads();

    if (s_last) {
        float* fs = (float*)xs;          // reuse staging buffer: [64][9]
        for (int p = tid; p < B_SLIDES * 9; p += TPB) {
            int bb = p / 9, k = p % 9;
            float s = 0.f;
            #pragma unroll
            for (int c = 0; c < CHUNKS; ++c)
                s += ldcg(&g_partials[((size_t)bb * CHUNKS + c) * 9 + k]);
            fs[bb * 9 + k] = s;
        }
        __syncthreads();
        if (tid < B_SLIDES) {
            float inv = 1.f / fs[tid * 9];
            #pragma unroll
            for (int o = 0; o < N_OUT; ++o) {
                float r = b4[o];
                #pragma unroll
                for (int k = 0; k < H2; ++k)
                    r += (fs[tid * 9 + 1 + k] * inv) * W4[k * N_OUT + o];
                out[tid * N_OUT + o] = r;
            }
        }
        if (tid == 0) atomicExch(&g_count, 0u);   // reset for next graph replay
    }
}

extern "C" void kernel_launch(void* const* d_in, const int* in_sizes, int n_in,
                              void* d_out, int out_size)
{
    (void)in_sizes; (void)n_in; (void)out_size;

    // W1 + b1 into constant memory (raw D2D copies, graph-capturable).
    cudaMemcpyToSymbolAsync(cW1p, d_in[1], NI * H1 * sizeof(float), 0,
                            cudaMemcpyDeviceToDevice, 0);
    cudaMemcpyToSymbolAsync(cb1,  d_in[2], H1 * sizeof(float), 0,
                            cudaMemcpyDeviceToDevice, 0);

    cudaFuncSetAttribute(mlp_pool_kernel,
                         cudaFuncAttributeMaxDynamicSharedMemorySize, SMEM_BYTES);
    dim3 grid(CHUNKS, B_SLIDES);
    mlp_pool_kernel<<<grid, TPB, SMEM_BYTES>>>(
        (const float*)d_in[0],
        (const float*)d_in[1],
        (const float*)d_in[3], (const float*)d_in[4],
        (const float*)d_in[5], (const float*)d_in[6],
        (const float*)d_in[7], (const float*)d_in[8],
        (float*)d_out);
}